// round 14
// baseline (speedup 1.0000x reference)
#include <cuda_runtime.h>
#include <cuda_fp16.h>
#include <cstdint>
#include <cfloat>

namespace {
constexpr int S = 2048, E = 1024, H = 16, D = 64, B = 4;
constexpr int MALL = B * S;  // 8192
constexpr long long NX = (long long)MALL * E;   // x elems
constexpr long long NW = (long long)E * E;      // per-W elems
}

// Scratch (allocation-free: __device__ globals)
__device__ __half g_xh [(size_t)MALL * E];        // x in fp16
__device__ __half g_Wh [(size_t)4 * E * E];       // Wq|Wk|Wv|Wo fp16 (QKV contiguous)
__device__ __half g_Qh [(size_t)B * H * S * D];   // [B,H,S,D], pre-scaled by 0.125*log2(e)
__device__ __half g_Kh [(size_t)B * H * S * D];   // [B,H,S,D]
__device__ __half g_Vth[(size_t)B * H * D * S];   // [B,H,D,S]
__device__ __half g_Ph [(size_t)B * H * S * S];   // UNNORMALIZED exp(scores), fp16
__device__ float  g_invs[(size_t)B * H * S];      // 1/rowsum per (b,h,s)
__device__ __half g_ctxh[(size_t)B * S * E];      // [B,S,E]

namespace {
struct AsyncCtx {
    cudaStream_t s2 = nullptr;
    cudaEvent_t e1 = nullptr, e2 = nullptr, e3 = nullptr;
    bool ok = false;
    AsyncCtx() {
        ok = cudaStreamCreateWithFlags(&s2, cudaStreamNonBlocking) == cudaSuccess
          && cudaEventCreateWithFlags(&e1, cudaEventDisableTiming) == cudaSuccess
          && cudaEventCreateWithFlags(&e2, cudaEventDisableTiming) == cudaSuccess
          && cudaEventCreateWithFlags(&e3, cudaEventDisableTiming) == cudaSuccess;
    }
};
AsyncCtx g_async;
}

__device__ __forceinline__ uint32_t smem_u32(const void* p) {
    uint32_t a;
    asm("{ .reg .u64 t; cvta.to.shared.u64 t, %1; cvt.u32.u64 %0, t; }" : "=r"(a) : "l"(p));
    return a;
}
__device__ __forceinline__ void mma16(float* c, const uint32_t* a, const uint32_t* b) {
    asm volatile(
        "mma.sync.aligned.m16n8k16.row.col.f32.f16.f16.f32 "
        "{%0,%1,%2,%3}, {%4,%5,%6,%7}, {%8,%9}, {%0,%1,%2,%3};"
        : "+f"(c[0]), "+f"(c[1]), "+f"(c[2]), "+f"(c[3])
        : "r"(a[0]), "r"(a[1]), "r"(a[2]), "r"(a[3]), "r"(b[0]), "r"(b[1]));
}
__device__ __forceinline__ uint32_t packh2(float a, float b) {
    __half2 h = __floats2half2_rn(a, b);
    return *reinterpret_cast<uint32_t*>(&h);
}
__device__ __forceinline__ uint32_t h2ex2(uint32_t x) {
    uint32_t r;
    asm("ex2.approx.f16x2 %0, %1;" : "=r"(r) : "r"(x));
    return r;
}
#define LDSM4(r0, r1, r2, r3, addr) \
    asm volatile("ldmatrix.sync.aligned.m8n8.x4.shared.b16 {%0,%1,%2,%3}, [%4];" \
        : "=r"(r0), "=r"(r1), "=r"(r2), "=r"(r3) : "r"(addr))

// exp2 pre-scale folded into Q: exp(s*0.125) == exp2(s*QSCALE)
#define QSCALE 0.1803368801111204f   // 0.125 * log2(e)

// ---------------- merged fp32 -> fp16 convert (x + 4 weights, one launch) ----------------
__global__ void __launch_bounds__(256) f2h5(
    const float* __restrict__ x,
    const float* __restrict__ Wq, const float* __restrict__ Wk,
    const float* __restrict__ Wv, const float* __restrict__ Wo,
    __half* __restrict__ xh, __half* __restrict__ Wh)
{
    constexpr int XCTAS = (int)(NX / 1024);   // 8192
    constexpr int WCTAS = (int)(NW / 1024);   // 1024
    const int bid = blockIdx.x;
    const float* src;
    __half* dst;
    long long off;
    if (bid < XCTAS) {
        src = x; dst = xh;
        off = (long long)bid * 1024 + threadIdx.x * 4;
    } else {
        const int w = (bid - XCTAS) / WCTAS;       // 0..3
        const int wo = (bid - XCTAS) % WCTAS;
        src = (w == 0) ? Wq : (w == 1) ? Wk : (w == 2) ? Wv : Wo;
        dst = Wh + (long long)w * NW;
        off = (long long)wo * 1024 + threadIdx.x * 4;
    }
    float4 v = *(const float4*)(src + off);
    *(__half2*)(dst + off)     = __floats2half2_rn(v.x, v.y);
    *(__half2*)(dst + off + 2) = __floats2half2_rn(v.z, v.w);
}

// ---------------- fused QK^T -> exp2(f16x2) -> {Ph, rowsums} + P@V -> ctx ----------------
// grid (S/128, nBH), 256 threads; bh = bhBase + blockIdx.y.
__global__ void __launch_bounds__(256) qk_pv(
    const __half* __restrict__ Qg, const __half* __restrict__ Kg,
    const __half* __restrict__ Vtg,
    __half* __restrict__ Ph, float* __restrict__ invs, __half* __restrict__ ctx,
    int bhBase)
{
    constexpr int KB_ = 128 * 144;
    constexpr int VB_ = 64 * 272;
    constexpr int QOFF = 0;
    constexpr int KOFF = KB_;
    constexpr int VOFF = KOFF + 3 * KB_;
    constexpr int REDOFF = VOFF + 3 * VB_;
    constexpr int INVOFF = REDOFF + 4096;
    constexpr int EXOFF = KOFF;

    extern __shared__ char smc[];
    const uint32_t sb = smem_u32(smc);
    const int tid = threadIdx.x, lane = tid & 31, wid = tid >> 5;
    const int wm = wid >> 1, wn = wid & 1;
    const int g = lane >> 2, t = lane & 3;
    const int m0 = blockIdx.x * 128;
    const int bh = bhBase + blockIdx.y;
    const int bb = bh >> 4, h = bh & (H - 1);
    const __half* __restrict__ Qb = Qg + ((long long)bh * S + m0) * D;
    const __half* __restrict__ Kb = Kg + (long long)bh * S * D;
    const __half* __restrict__ Vb = Vtg + (long long)bh * D * S;
    __half* __restrict__ Pb = Ph + ((long long)bh * S + m0) * S;

#pragma unroll
    for (int l = 0; l < 4; l++) {
        const int lin = tid + l * 256, row = lin >> 3, kq = lin & 7;
        asm volatile("cp.async.cg.shared.global [%0], [%1], 16;"
                     :: "r"(sb + QOFF + row * 144 + kq * 16), "l"(Qb + row * D + kq * 8));
    }
    auto loadKV = [&](int nt, int buf) {
        const __half* ks = Kb + (long long)nt * 128 * D;
        const uint32_t kd = sb + KOFF + (uint32_t)buf * KB_;
#pragma unroll
        for (int l = 0; l < 4; l++) {
            const int lin = tid + l * 256, row = lin >> 3, kq = lin & 7;
            asm volatile("cp.async.cg.shared.global [%0], [%1], 16;"
                         :: "r"(kd + row * 144 + kq * 16), "l"(ks + row * D + kq * 8));
        }
        const __half* vs = Vb + nt * 128;
        const uint32_t vd = sb + VOFF + (uint32_t)buf * VB_;
#pragma unroll
        for (int l = 0; l < 4; l++) {
            const int lin = tid + l * 256, row = lin >> 4, sg = lin & 15;
            asm volatile("cp.async.cg.shared.global [%0], [%1], 16;"
                         :: "r"(vd + row * 272 + sg * 16), "l"(vs + (long long)row * S + sg * 8));
        }
        asm volatile("cp.async.commit_group;" ::: "memory");
    };

    const uint32_t a_lane = (uint32_t)((lane & 15) * 144 + ((lane >> 4) << 4));
    const uint32_t b_lane = (uint32_t)((((lane & 7) | ((lane >> 4) << 3)) * 144) + ((lane & 8) << 1));
    const uint32_t bv_lane = (uint32_t)((((lane & 7) | ((lane >> 4) << 3)) * 272) + ((lane & 8) << 1));
    const uint32_t abase = sb + QOFF + (uint32_t)(wm * 32) * 144 + a_lane;

    loadKV(0, 0);
    loadKV(1, 1);

    float rs[4] = {0.f, 0.f, 0.f, 0.f};
    float ctxa[2][8][4];
#pragma unroll
    for (int i = 0; i < 2; i++)
#pragma unroll
        for (int j = 0; j < 8; j++)
#pragma unroll
            for (int r = 0; r < 4; r++) ctxa[i][j][r] = 0.f;

    for (int nt = 0; nt < 16; nt++) {
        if (nt + 1 < 16) asm volatile("cp.async.wait_group 1;" ::: "memory");
        else             asm volatile("cp.async.wait_group 0;" ::: "memory");
        __syncthreads();
        if (nt + 2 < 16) loadKV(nt + 2, (nt + 2) % 3);

        float acc[2][8][4];
#pragma unroll
        for (int i = 0; i < 2; i++)
#pragma unroll
            for (int j = 0; j < 8; j++)
#pragma unroll
                for (int r = 0; r < 4; r++) acc[i][j][r] = 0.f;

        const uint32_t bbase = sb + KOFF + (uint32_t)(nt % 3) * KB_
                             + (uint32_t)(wn * 64) * 144 + b_lane;
        uint32_t bf[2][8][2];
#pragma unroll
        for (int jp = 0; jp < 4; jp++)
            LDSM4(bf[0][2 * jp][0], bf[0][2 * jp][1], bf[0][2 * jp + 1][0], bf[0][2 * jp + 1][1],
                  bbase + jp * 16 * 144);
#pragma unroll
        for (int ks = 0; ks < 4; ks++) {
            const int cur = ks & 1;
            uint32_t af[2][4];
            LDSM4(af[0][0], af[0][1], af[0][2], af[0][3], abase + ks * 32);
            LDSM4(af[1][0], af[1][1], af[1][2], af[1][3], abase + 16 * 144 + ks * 32);
            if (ks < 3) {
#pragma unroll
                for (int jp = 0; jp < 4; jp++)
                    LDSM4(bf[cur ^ 1][2 * jp][0], bf[cur ^ 1][2 * jp][1],
                          bf[cur ^ 1][2 * jp + 1][0], bf[cur ^ 1][2 * jp + 1][1],
                          bbase + jp * 16 * 144 + (ks + 1) * 32);
            }
#pragma unroll
            for (int i = 0; i < 2; i++)
#pragma unroll
                for (int j = 0; j < 8; j++)
                    mma16(acc[i][j], af[i], bf[cur][j]);
        }

        // pack scores -> f16x2, one MUFU exp2 per pair; feeds Ph, rowsums, PV A-frags.
        uint32_t eh[2][8][2];
        const int n0 = nt * 128;
#pragma unroll
        for (int i = 0; i < 2; i++) {
            const int r0 = wm * 32 + i * 16 + g;
#pragma unroll
            for (int j = 0; j < 8; j++) {
                const int cn = n0 + wn * 64 + j * 8 + 2 * t;
                const uint32_t e01 = h2ex2(packh2(acc[i][j][0], acc[i][j][1]));
                const uint32_t e23 = h2ex2(packh2(acc[i][j][2], acc[i][j][3]));
                eh[i][j][0] = e01;
                eh[i][j][1] = e23;
                *(uint32_t*)&Pb[(long long)r0 * S + cn]       = e01;
                *(uint32_t*)&Pb[(long long)(r0 + 8) * S + cn] = e23;
                const float2 f01 = __half22float2(*reinterpret_cast<const __half2*>(&e01));
                const float2 f23 = __half22float2(*reinterpret_cast<const __half2*>(&e23));
                rs[2 * i]     += f01.x + f01.y;
                rs[2 * i + 1] += f23.x + f23.y;
            }
        }

        const uint32_t vbase = sb + VOFF + (uint32_t)(nt % 3) * VB_ + bv_lane
                             + (uint32_t)(wn * 64) * 2;
#pragma unroll
        for (int kb = 0; kb < 4; kb++) {
            uint32_t pa[2][4];
#pragma unroll
            for (int i = 0; i < 2; i++) {
                pa[i][0] = eh[i][2 * kb][0];
                pa[i][1] = eh[i][2 * kb][1];
                pa[i][2] = eh[i][2 * kb + 1][0];
                pa[i][3] = eh[i][2 * kb + 1][1];
            }
            uint32_t bv[8][2];
#pragma unroll
            for (int jp = 0; jp < 4; jp++)
                LDSM4(bv[2 * jp][0], bv[2 * jp][1], bv[2 * jp + 1][0], bv[2 * jp + 1][1],
                      vbase + jp * 16 * 272 + kb * 32);
#pragma unroll
            for (int i = 0; i < 2; i++)
#pragma unroll
                for (int j = 0; j < 8; j++)
                    mma16(ctxa[i][j], pa[i], bv[j]);
        }
    }

    __syncthreads();
    float* red = (float*)(smc + REDOFF);
    float* inv_sm = (float*)(smc + INVOFF);
    const int slot = wn * 4 + t;
#pragma unroll
    for (int i = 0; i < 2; i++) {
        red[(wm * 32 + i * 16 + g) * 8 + slot]     = rs[2 * i];
        red[(wm * 32 + i * 16 + g + 8) * 8 + slot] = rs[2 * i + 1];
    }
    __syncthreads();
    if (tid < 128) {
        float s = 0.f;
#pragma unroll
        for (int q = 0; q < 8; q++) s += red[tid * 8 + q];
        const float iv = 1.f / s;
        inv_sm[tid] = iv;
        invs[(long long)bh * S + m0 + tid] = iv;
    }
    if (wn == 1) {
        float* ex_ = (float*)(smc + EXOFF) + wm * 2048;
#pragma unroll
        for (int i = 0; i < 2; i++)
#pragma unroll
            for (int j = 0; j < 8; j++) {
                const int c0 = j * 8 + 2 * t;
                ex_[(i * 16 + g) * 64 + c0]           = ctxa[i][j][0];
                ex_[(i * 16 + g) * 64 + c0 + 1]       = ctxa[i][j][1];
                ex_[(i * 16 + g + 8) * 64 + c0]       = ctxa[i][j][2];
                ex_[(i * 16 + g + 8) * 64 + c0 + 1]   = ctxa[i][j][3];
            }
    }
    __syncthreads();
    if (wn == 0) {
        const float* ex_ = (const float*)(smc + EXOFF) + wm * 2048;
#pragma unroll
        for (int i = 0; i < 2; i++) {
            const int rl0 = wm * 32 + i * 16 + g;
            const float iv0 = inv_sm[rl0], iv1 = inv_sm[rl0 + 8];
            const int m_0 = m0 + rl0;
#pragma unroll
            for (int j = 0; j < 8; j++) {
                const int c0 = j * 8 + 2 * t;
                const float v0 = (ctxa[i][j][0] + ex_[(i * 16 + g) * 64 + c0])     * iv0;
                const float v1 = (ctxa[i][j][1] + ex_[(i * 16 + g) * 64 + c0 + 1]) * iv0;
                const float v2 = (ctxa[i][j][2] + ex_[(i * 16 + g + 8) * 64 + c0])     * iv1;
                const float v3 = (ctxa[i][j][3] + ex_[(i * 16 + g + 8) * 64 + c0 + 1]) * iv1;
                __half* d0 = ctx + ((long long)bb * S + m_0) * E + h * D + c0;
                __half* d1 = ctx + ((long long)bb * S + m_0 + 8) * E + h * D + c0;
                *(__half2*)d0 = __floats2half2_rn(v0, v1);
                *(__half2*)d1 = __floats2half2_rn(v2, v3);
            }
        }
    }
}

// ---------------- fp16 TN GEMM (256 thr / 8 warps, warp tile 32x64) ----------------
// MODE 0: fp32 out[m*N+n]+bias   MODE 5: fused QKV scatter (sector = n>>10; Q pre-scaled)
template <int BN, int MODE>
__global__ void __launch_bounds__(256, 2) gemm_h(
    const __half* __restrict__ A, const __half* __restrict__ Bm,
    void* __restrict__ Cv,
    const float* __restrict__ bias0, const float* __restrict__ bias1,
    const float* __restrict__ bias2,
    int N, int K)
{
    constexpr int ABUFB = 128 * 144;
    constexpr int BBUFB = BN * 144;
    constexpr int NTJ = BN / 16;

    extern __shared__ char smc[];
    const uint32_t sb = smem_u32(smc);
    const int tid = threadIdx.x, lane = tid & 31, wid = tid >> 5;
    const int wm = wid >> 1, wn = wid & 1;
    const int g = lane >> 2, t = lane & 3;
    const int m0 = blockIdx.y * 128, n0 = blockIdx.x * BN;

    float acc[2][NTJ][4];
#pragma unroll
    for (int i = 0; i < 2; i++)
#pragma unroll
        for (int j = 0; j < NTJ; j++)
#pragma unroll
            for (int r = 0; r < 4; r++) acc[i][j][r] = 0.f;

    auto load = [&](int chunk, int buf) {
        const int k0 = chunk * 64;
        const uint32_t ad = sb + (uint32_t)buf * ABUFB;
#pragma unroll
        for (int l = 0; l < 4; l++) {
            const int lin = tid + l * 256, row = lin >> 3, kq = lin & 7;
            const __half* src = A + (long long)(m0 + row) * K + k0 + kq * 8;
            asm volatile("cp.async.cg.shared.global [%0], [%1], 16;"
                         :: "r"(ad + row * 144 + kq * 16), "l"(src));
        }
        const uint32_t bd = sb + (uint32_t)(3 * ABUFB + buf * BBUFB);
#pragma unroll
        for (int l = 0; l < BN / 32; l++) {
            const int lin = tid + l * 256, row = lin >> 3, kq = lin & 7;
            const __half* src = Bm + (long long)(n0 + row) * K + k0 + kq * 8;
            asm volatile("cp.async.cg.shared.global [%0], [%1], 16;"
                         :: "r"(bd + row * 144 + kq * 16), "l"(src));
        }
        asm volatile("cp.async.commit_group;" ::: "memory");
    };

    const uint32_t a_lane = (uint32_t)((lane & 15) * 144 + ((lane >> 4) << 4));
    const uint32_t b_lane = (uint32_t)((((lane & 7) | ((lane >> 4) << 3)) * 144) + ((lane & 8) << 1));

    auto compute = [&](int buf) {
        const uint32_t abase = sb + (uint32_t)buf * ABUFB + (uint32_t)(wm * 32) * 144 + a_lane;
        const uint32_t bbase = sb + (uint32_t)(3 * ABUFB + buf * BBUFB)
                             + (uint32_t)(wn * (BN / 2)) * 144 + b_lane;
        uint32_t bf[2][NTJ][2];
#pragma unroll
        for (int jp = 0; jp < NTJ / 2; jp++)
            LDSM4(bf[0][2 * jp][0], bf[0][2 * jp][1], bf[0][2 * jp + 1][0], bf[0][2 * jp + 1][1],
                  bbase + jp * 16 * 144);
#pragma unroll
        for (int ks = 0; ks < 4; ks++) {
            const int cur = ks & 1;
            uint32_t af[2][4];
            LDSM4(af[0][0], af[0][1], af[0][2], af[0][3], abase + ks * 32);
            LDSM4(af[1][0], af[1][1], af[1][2], af[1][3], abase + 16 * 144 + ks * 32);
            if (ks < 3) {
#pragma unroll
                for (int jp = 0; jp < NTJ / 2; jp++)
                    LDSM4(bf[cur ^ 1][2 * jp][0], bf[cur ^ 1][2 * jp][1],
                          bf[cur ^ 1][2 * jp + 1][0], bf[cur ^ 1][2 * jp + 1][1],
                          bbase + jp * 16 * 144 + (ks + 1) * 32);
            }
#pragma unroll
            for (int i = 0; i < 2; i++)
#pragma unroll
                for (int j = 0; j < NTJ; j++)
                    mma16(acc[i][j], af[i], bf[cur][j]);
        }
    };

    const int NC = K / 64;
    load(0, 0);
    if (NC > 1) load(1, 1);
    for (int c = 0; c < NC; c++) {
        if (c + 1 < NC) asm volatile("cp.async.wait_group 1;" ::: "memory");
        else            asm volatile("cp.async.wait_group 0;" ::: "memory");
        __syncthreads();
        if (c + 2 < NC) load(c + 2, (c + 2) % 3);
        compute(c % 3);
    }

    float* Cf = (float*)Cv;
    const int sec = n0 >> 10;
    const float* bsel = (MODE == 5) ? (sec == 0 ? bias0 : sec == 1 ? bias1 : bias2) : bias0;
#pragma unroll
    for (int i = 0; i < 2; i++) {
        const int r0 = m0 + wm * 32 + i * 16 + g;
#pragma unroll
        for (int j = 0; j < NTJ; j++) {
            const int cn = n0 + wn * (BN / 2) + j * 8 + 2 * t;
            float c0 = acc[i][j][0], c1 = acc[i][j][1];
            float c2 = acc[i][j][2], c3 = acc[i][j][3];
            if constexpr (MODE == 0) {
                const float b0 = bias0[cn], b1 = bias0[cn + 1];
                *(float2*)&Cf[(long long)r0 * N + cn]       = make_float2(c0 + b0, c1 + b1);
                *(float2*)&Cf[(long long)(r0 + 8) * N + cn] = make_float2(c2 + b0, c3 + b1);
            } else {  // MODE 5
                const int nn = cn & 1023;
                const float b0 = bsel[nn], b1 = bsel[nn + 1];
                const int hh = nn >> 6, d = nn & (D - 1);
                if (sec < 2) {
                    const float sc = (sec == 0) ? QSCALE : 1.f;
                    __half* dst = sec == 0 ? g_Qh : g_Kh;
                    auto idx = [&](int m) {
                        return (((long long)(m >> 11) * H + hh) * S + (m & (S - 1))) * D + d;
                    };
                    *(__half2*)&dst[idx(r0)]     = __floats2half2_rn((c0 + b0) * sc, (c1 + b1) * sc);
                    *(__half2*)&dst[idx(r0 + 8)] = __floats2half2_rn((c2 + b0) * sc, (c3 + b1) * sc);
                } else {
                    auto idx = [&](int m, int dd) {
                        return (((long long)(m >> 11) * H + hh) * D + dd) * S + (m & (S - 1));
                    };
                    g_Vth[idx(r0, d)]         = __float2half_rn(c0 + b0);
                    g_Vth[idx(r0, d + 1)]     = __float2half_rn(c1 + b1);
                    g_Vth[idx(r0 + 8, d)]     = __float2half_rn(c2 + b0);
                    g_Vth[idx(r0 + 8, d + 1)] = __float2half_rn(c3 + b1);
                }
            }
        }
    }
}

// ---------------- head average (b = b0 + blockIdx.y) ----------------
__global__ void __launch_bounds__(256) avg_heads(const __half* __restrict__ Ph,
                                                 const float* __restrict__ invs,
                                                 float* __restrict__ attn, int b0)
{
    const int sq = blockIdx.x, b = b0 + blockIdx.y;
    const int c = threadIdx.x * 8;
    const __half* p = Ph + (((long long)b * H) * S + sq) * S + c;
    const float* iv = invs + (long long)b * H * S + sq;

    float a[8] = {0.f, 0.f, 0.f, 0.f, 0.f, 0.f, 0.f, 0.f};
#pragma unroll
    for (int h = 0; h < H; h++) {
        const float inv = iv[(long long)h * S];
        uint2 u0 = *(const uint2*)(p);
        uint2 u1 = *(const uint2*)(p + 4);
        float2 f0 = __half22float2(*reinterpret_cast<__half2*>(&u0.x));
        float2 f1 = __half22float2(*reinterpret_cast<__half2*>(&u0.y));
        float2 f2 = __half22float2(*reinterpret_cast<__half2*>(&u1.x));
        float2 f3 = __half22float2(*reinterpret_cast<__half2*>(&u1.y));
        a[0] += f0.x * inv; a[1] += f0.y * inv;
        a[2] += f1.x * inv; a[3] += f1.y * inv;
        a[4] += f2.x * inv; a[5] += f2.y * inv;
        a[6] += f3.x * inv; a[7] += f3.y * inv;
        p += (long long)S * S;
    }
    const float s16 = 1.f / 16.f;
    float* o = attn + ((long long)b * S + sq) * S + c;
    *(float4*)(o)     = make_float4(a[0] * s16, a[1] * s16, a[2] * s16, a[3] * s16);
    *(float4*)(o + 4) = make_float4(a[4] * s16, a[5] * s16, a[6] * s16, a[7] * s16);
}

// ---------------- launch ----------------
extern "C" void kernel_launch(void* const* d_in, const int* in_sizes, int n_in,
                              void* d_out, int out_size)
{
    (void)in_sizes; (void)n_in; (void)out_size;
    const float* x  = (const float*)d_in[0];
    const float* Wq = (const float*)d_in[1];
    const float* bq = (const float*)d_in[2];
    const float* Wk = (const float*)d_in[3];
    const float* bk = (const float*)d_in[4];
    const float* Wv = (const float*)d_in[5];
    const float* bv = (const float*)d_in[6];
    const float* Wo = (const float*)d_in[7];
    const float* bo = (const float*)d_in[8];
    float* out  = (float*)d_out;
    float* attn = out + (long long)B * S * E;

    __half *pxh, *pWh, *pQ, *pK, *pVt, *pPh, *pCtx;
    float *pInv;
    cudaGetSymbolAddress((void**)&pxh, g_xh);
    cudaGetSymbolAddress((void**)&pWh, g_Wh);
    cudaGetSymbolAddress((void**)&pQ, g_Qh);
    cudaGetSymbolAddress((void**)&pK, g_Kh);
    cudaGetSymbolAddress((void**)&pVt, g_Vth);
    cudaGetSymbolAddress((void**)&pPh, g_Ph);
    cudaGetSymbolAddress((void**)&pInv, g_invs);
    cudaGetSymbolAddress((void**)&pCtx, g_ctxh);

    constexpr int SMEM_G    = 3 * 128 * 144 + 3 * 128 * 144;          // 110592
    constexpr int SMEM_QKPV = 18432 + 3 * 18432 + 3 * 17408 + 4608;   // 130560
    cudaFuncSetAttribute(gemm_h<128, 0>, cudaFuncAttributeMaxDynamicSharedMemorySize, SMEM_G);
    cudaFuncSetAttribute(gemm_h<128, 5>, cudaFuncAttributeMaxDynamicSharedMemorySize, SMEM_G);
    cudaFuncSetAttribute(qk_pv,          cudaFuncAttributeMaxDynamicSharedMemorySize, SMEM_QKPV);

    // merged fp32 -> fp16 conversions (x + 4 weights)
    f2h5<<<(unsigned)(NX / 1024 + 4 * (NW / 1024)), 256>>>(x, Wq, Wk, Wv, Wo, pxh, pWh);

    // Fused QKV projection (N = 3072); Q sector pre-scaled by QSCALE
    dim3 gqkv(3 * E / 128, MALL / 128, 1);
    gemm_h<128, 5><<<gqkv, 256, SMEM_G>>>(pxh, pWh, nullptr, bq, bk, bv, 3 * E, E);

    const bool forked = g_async.ok;
    constexpr int HBH = B * H / 2;  // 32

    // First half of batches: bh in [0, 32)
    qk_pv<<<dim3(S / 128, HBH), 256, SMEM_QKPV>>>(pQ, pK, pVt, pPh, pInv, pCtx, 0);
    if (forked) {
        cudaEventRecord(g_async.e1, 0);
        cudaStreamWaitEvent(g_async.s2, g_async.e1, 0);
        avg_heads<<<dim3(S, B / 2), 256, 0, g_async.s2>>>(pPh, pInv, attn, 0);
    }

    // Second half: bh in [32, 64) — overlaps avg(b0,b1) on s2
    qk_pv<<<dim3(S / 128, HBH), 256, SMEM_QKPV>>>(pQ, pK, pVt, pPh, pInv, pCtx, HBH);
    if (forked) {
        cudaEventRecord(g_async.e2, 0);
        cudaStreamWaitEvent(g_async.s2, g_async.e2, 0);
        avg_heads<<<dim3(S, B / 2), 256, 0, g_async.s2>>>(pPh, pInv, attn, B / 2);
        cudaEventRecord(g_async.e3, g_async.s2);
    } else {
        avg_heads<<<dim3(S, B / 2), 256>>>(pPh, pInv, attn, 0);
        avg_heads<<<dim3(S, B / 2), 256>>>(pPh, pInv, attn, B / 2);
    }

    // out = ctx @ Wo^T + bo — overlaps avg(b2,b3) on s2
    dim3 gproj(E / 128, MALL / 128, 1);
    gemm_h<128, 0><<<gproj, 256, SMEM_G>>>(pCtx, pWh + 3ll * E * E, out, bo,
                                           nullptr, nullptr, E, E);

    if (forked) cudaStreamWaitEvent(0, g_async.e3, 0);
}

// round 15
// speedup vs baseline: 1.0843x; 1.0843x over previous
#include <cuda_runtime.h>
#include <cuda_fp16.h>
#include <cstdint>
#include <cfloat>

namespace {
constexpr int S = 2048, E = 1024, H = 16, D = 64, B = 4;
constexpr int MALL = B * S;  // 8192
constexpr long long NX = (long long)MALL * E;   // x elems
constexpr long long NW = (long long)E * E;      // per-W elems
}

// Scratch (allocation-free: __device__ globals)
__device__ __half g_xh [(size_t)MALL * E];        // x in fp16
__device__ __half g_Wh [(size_t)4 * E * E];       // Wq|Wk|Wv|Wo fp16 (QKV contiguous)
__device__ __half g_Qh [(size_t)B * H * S * D];   // [B,H,S,D], pre-scaled by 0.125*log2(e)
__device__ __half g_Kh [(size_t)B * H * S * D];   // [B,H,S,D]
__device__ __half g_Vth[(size_t)B * H * D * S];   // [B,H,D,S]
__device__ __half g_Ph [(size_t)B * H * S * S];   // UNNORMALIZED exp(scores), fp16
__device__ float  g_invs[(size_t)B * H * S];      // 1/rowsum per (b,h,s)
__device__ __half g_ctxh[(size_t)B * S * E];      // [B,S,E]

namespace {
struct AsyncCtx {
    cudaStream_t s2 = nullptr;
    cudaEvent_t e1 = nullptr, e2 = nullptr;
    bool ok = false;
    AsyncCtx() {
        ok = cudaStreamCreateWithFlags(&s2, cudaStreamNonBlocking) == cudaSuccess
          && cudaEventCreateWithFlags(&e1, cudaEventDisableTiming) == cudaSuccess
          && cudaEventCreateWithFlags(&e2, cudaEventDisableTiming) == cudaSuccess;
    }
};
AsyncCtx g_async;
}

__device__ __forceinline__ uint32_t smem_u32(const void* p) {
    uint32_t a;
    asm("{ .reg .u64 t; cvta.to.shared.u64 t, %1; cvt.u32.u64 %0, t; }" : "=r"(a) : "l"(p));
    return a;
}
__device__ __forceinline__ void mma16(float* c, const uint32_t* a, const uint32_t* b) {
    asm volatile(
        "mma.sync.aligned.m16n8k16.row.col.f32.f16.f16.f32 "
        "{%0,%1,%2,%3}, {%4,%5,%6,%7}, {%8,%9}, {%0,%1,%2,%3};"
        : "+f"(c[0]), "+f"(c[1]), "+f"(c[2]), "+f"(c[3])
        : "r"(a[0]), "r"(a[1]), "r"(a[2]), "r"(a[3]), "r"(b[0]), "r"(b[1]));
}
__device__ __forceinline__ uint32_t packh2(float a, float b) {
    __half2 h = __floats2half2_rn(a, b);
    return *reinterpret_cast<uint32_t*>(&h);
}
// fp16x2 exp2: one MUFU per pair
__device__ __forceinline__ uint32_t h2ex2(uint32_t x) {
    uint32_t r;
    asm("ex2.approx.f16x2 %0, %1;" : "=r"(r) : "r"(x));
    return r;
}
#define LDSM4(r0, r1, r2, r3, addr) \
    asm volatile("ldmatrix.sync.aligned.m8n8.x4.shared.b16 {%0,%1,%2,%3}, [%4];" \
        : "=r"(r0), "=r"(r1), "=r"(r2), "=r"(r3) : "r"(addr))

// exp2 pre-scale folded into Q: exp(s*0.125) == exp2(s*QSCALE)
#define QSCALE 0.1803368801111204f   // 0.125 * log2(e)

// ---------------- merged fp32 -> fp16 convert (x + 4 weights, one launch) ----------------
__global__ void __launch_bounds__(256) f2h5(
    const float* __restrict__ x,
    const float* __restrict__ Wq, const float* __restrict__ Wk,
    const float* __restrict__ Wv, const float* __restrict__ Wo,
    __half* __restrict__ xh, __half* __restrict__ Wh)
{
    constexpr int XCTAS = (int)(NX / 1024);   // 8192
    constexpr int WCTAS = (int)(NW / 1024);   // 1024
    const int bid = blockIdx.x;
    const float* src;
    __half* dst;
    long long off;
    if (bid < XCTAS) {
        src = x; dst = xh;
        off = (long long)bid * 1024 + threadIdx.x * 4;
    } else {
        const int w = (bid - XCTAS) / WCTAS;       // 0..3
        const int wo = (bid - XCTAS) % WCTAS;
        src = (w == 0) ? Wq : (w == 1) ? Wk : (w == 2) ? Wv : Wo;
        dst = Wh + (long long)w * NW;
        off = (long long)wo * 1024 + threadIdx.x * 4;
    }
    float4 v = *(const float4*)(src + off);
    *(__half2*)(dst + off)     = __floats2half2_rn(v.x, v.y);
    *(__half2*)(dst + off + 2) = __floats2half2_rn(v.z, v.w);
}

// ---------------- fused QK^T -> exp2(f16x2) -> {Ph, rowsums} + P@V -> ctx ----------------
// grid (S/128, B*H), 256 threads. Q pre-scaled; probs = ex2.f16x2(pack(scores)).
__global__ void __launch_bounds__(256) qk_pv(
    const __half* __restrict__ Qg, const __half* __restrict__ Kg,
    const __half* __restrict__ Vtg,
    __half* __restrict__ Ph, float* __restrict__ invs, __half* __restrict__ ctx)
{
    constexpr int KB_ = 128 * 144;
    constexpr int VB_ = 64 * 272;
    constexpr int QOFF = 0;
    constexpr int KOFF = KB_;
    constexpr int VOFF = KOFF + 3 * KB_;
    constexpr int REDOFF = VOFF + 3 * VB_;
    constexpr int INVOFF = REDOFF + 4096;
    constexpr int EXOFF = KOFF;

    extern __shared__ char smc[];
    const uint32_t sb = smem_u32(smc);
    const int tid = threadIdx.x, lane = tid & 31, wid = tid >> 5;
    const int wm = wid >> 1, wn = wid & 1;
    const int g = lane >> 2, t = lane & 3;
    const int m0 = blockIdx.x * 128;
    const int bh = blockIdx.y;
    const int bb = bh >> 4, h = bh & (H - 1);
    const __half* __restrict__ Qb = Qg + ((long long)bh * S + m0) * D;
    const __half* __restrict__ Kb = Kg + (long long)bh * S * D;
    const __half* __restrict__ Vb = Vtg + (long long)bh * D * S;
    __half* __restrict__ Pb = Ph + ((long long)bh * S + m0) * S;

#pragma unroll
    for (int l = 0; l < 4; l++) {
        const int lin = tid + l * 256, row = lin >> 3, kq = lin & 7;
        asm volatile("cp.async.cg.shared.global [%0], [%1], 16;"
                     :: "r"(sb + QOFF + row * 144 + kq * 16), "l"(Qb + row * D + kq * 8));
    }
    auto loadKV = [&](int nt, int buf) {
        const __half* ks = Kb + (long long)nt * 128 * D;
        const uint32_t kd = sb + KOFF + (uint32_t)buf * KB_;
#pragma unroll
        for (int l = 0; l < 4; l++) {
            const int lin = tid + l * 256, row = lin >> 3, kq = lin & 7;
            asm volatile("cp.async.cg.shared.global [%0], [%1], 16;"
                         :: "r"(kd + row * 144 + kq * 16), "l"(ks + row * D + kq * 8));
        }
        const __half* vs = Vb + nt * 128;
        const uint32_t vd = sb + VOFF + (uint32_t)buf * VB_;
#pragma unroll
        for (int l = 0; l < 4; l++) {
            const int lin = tid + l * 256, row = lin >> 4, sg = lin & 15;
            asm volatile("cp.async.cg.shared.global [%0], [%1], 16;"
                         :: "r"(vd + row * 272 + sg * 16), "l"(vs + (long long)row * S + sg * 8));
        }
        asm volatile("cp.async.commit_group;" ::: "memory");
    };

    const uint32_t a_lane = (uint32_t)((lane & 15) * 144 + ((lane >> 4) << 4));
    const uint32_t b_lane = (uint32_t)((((lane & 7) | ((lane >> 4) << 3)) * 144) + ((lane & 8) << 1));
    const uint32_t bv_lane = (uint32_t)((((lane & 7) | ((lane >> 4) << 3)) * 272) + ((lane & 8) << 1));
    const uint32_t abase = sb + QOFF + (uint32_t)(wm * 32) * 144 + a_lane;

    loadKV(0, 0);
    loadKV(1, 1);

    float rs[4] = {0.f, 0.f, 0.f, 0.f};
    float ctxa[2][8][4];
#pragma unroll
    for (int i = 0; i < 2; i++)
#pragma unroll
        for (int j = 0; j < 8; j++)
#pragma unroll
            for (int r = 0; r < 4; r++) ctxa[i][j][r] = 0.f;

    for (int nt = 0; nt < 16; nt++) {
        if (nt + 1 < 16) asm volatile("cp.async.wait_group 1;" ::: "memory");
        else             asm volatile("cp.async.wait_group 0;" ::: "memory");
        __syncthreads();
        if (nt + 2 < 16) loadKV(nt + 2, (nt + 2) % 3);

        float acc[2][8][4];
#pragma unroll
        for (int i = 0; i < 2; i++)
#pragma unroll
            for (int j = 0; j < 8; j++)
#pragma unroll
                for (int r = 0; r < 4; r++) acc[i][j][r] = 0.f;

        const uint32_t bbase = sb + KOFF + (uint32_t)(nt % 3) * KB_
                             + (uint32_t)(wn * 64) * 144 + b_lane;
        uint32_t bf[2][8][2];
#pragma unroll
        for (int jp = 0; jp < 4; jp++)
            LDSM4(bf[0][2 * jp][0], bf[0][2 * jp][1], bf[0][2 * jp + 1][0], bf[0][2 * jp + 1][1],
                  bbase + jp * 16 * 144);
#pragma unroll
        for (int ks = 0; ks < 4; ks++) {
            const int cur = ks & 1;
            uint32_t af[2][4];
            LDSM4(af[0][0], af[0][1], af[0][2], af[0][3], abase + ks * 32);
            LDSM4(af[1][0], af[1][1], af[1][2], af[1][3], abase + 16 * 144 + ks * 32);
            if (ks < 3) {
#pragma unroll
                for (int jp = 0; jp < 4; jp++)
                    LDSM4(bf[cur ^ 1][2 * jp][0], bf[cur ^ 1][2 * jp][1],
                          bf[cur ^ 1][2 * jp + 1][0], bf[cur ^ 1][2 * jp + 1][1],
                          bbase + jp * 16 * 144 + (ks + 1) * 32);
            }
#pragma unroll
            for (int i = 0; i < 2; i++)
#pragma unroll
                for (int j = 0; j < 8; j++)
                    mma16(acc[i][j], af[i], bf[cur][j]);
        }

        // pack scores -> f16x2, one MUFU exp2 per pair; feeds Ph, rowsums, PV A-frags.
        uint32_t eh[2][8][2];
        const int n0 = nt * 128;
#pragma unroll
        for (int i = 0; i < 2; i++) {
            const int r0 = wm * 32 + i * 16 + g;
#pragma unroll
            for (int j = 0; j < 8; j++) {
                const int cn = n0 + wn * 64 + j * 8 + 2 * t;
                const uint32_t e01 = h2ex2(packh2(acc[i][j][0], acc[i][j][1]));
                const uint32_t e23 = h2ex2(packh2(acc[i][j][2], acc[i][j][3]));
                eh[i][j][0] = e01;
                eh[i][j][1] = e23;
                *(uint32_t*)&Pb[(long long)r0 * S + cn]       = e01;
                *(uint32_t*)&Pb[(long long)(r0 + 8) * S + cn] = e23;
                const float2 f01 = __half22float2(*reinterpret_cast<const __half2*>(&e01));
                const float2 f23 = __half22float2(*reinterpret_cast<const __half2*>(&e23));
                rs[2 * i]     += f01.x + f01.y;
                rs[2 * i + 1] += f23.x + f23.y;
            }
        }

        const uint32_t vbase = sb + VOFF + (uint32_t)(nt % 3) * VB_ + bv_lane
                             + (uint32_t)(wn * 64) * 2;
#pragma unroll
        for (int kb = 0; kb < 4; kb++) {
            uint32_t pa[2][4];
#pragma unroll
            for (int i = 0; i < 2; i++) {
                pa[i][0] = eh[i][2 * kb][0];
                pa[i][1] = eh[i][2 * kb][1];
                pa[i][2] = eh[i][2 * kb + 1][0];
                pa[i][3] = eh[i][2 * kb + 1][1];
            }
            uint32_t bv[8][2];
#pragma unroll
            for (int jp = 0; jp < 4; jp++)
                LDSM4(bv[2 * jp][0], bv[2 * jp][1], bv[2 * jp + 1][0], bv[2 * jp + 1][1],
                      vbase + jp * 16 * 272 + kb * 32);
#pragma unroll
            for (int i = 0; i < 2; i++)
#pragma unroll
                for (int j = 0; j < 8; j++)
                    mma16(ctxa[i][j], pa[i], bv[j]);
        }
    }

    __syncthreads();
    float* red = (float*)(smc + REDOFF);
    float* inv_sm = (float*)(smc + INVOFF);
    const int slot = wn * 4 + t;
#pragma unroll
    for (int i = 0; i < 2; i++) {
        red[(wm * 32 + i * 16 + g) * 8 + slot]     = rs[2 * i];
        red[(wm * 32 + i * 16 + g + 8) * 8 + slot] = rs[2 * i + 1];
    }
    __syncthreads();
    if (tid < 128) {
        float s = 0.f;
#pragma unroll
        for (int q = 0; q < 8; q++) s += red[tid * 8 + q];
        const float iv = 1.f / s;
        inv_sm[tid] = iv;
        invs[(long long)bh * S + m0 + tid] = iv;
    }
    if (wn == 1) {
        float* ex_ = (float*)(smc + EXOFF) + wm * 2048;
#pragma unroll
        for (int i = 0; i < 2; i++)
#pragma unroll
            for (int j = 0; j < 8; j++) {
                const int c0 = j * 8 + 2 * t;
                ex_[(i * 16 + g) * 64 + c0]           = ctxa[i][j][0];
                ex_[(i * 16 + g) * 64 + c0 + 1]       = ctxa[i][j][1];
                ex_[(i * 16 + g + 8) * 64 + c0]       = ctxa[i][j][2];
                ex_[(i * 16 + g + 8) * 64 + c0 + 1]   = ctxa[i][j][3];
            }
    }
    __syncthreads();
    if (wn == 0) {
        const float* ex_ = (const float*)(smc + EXOFF) + wm * 2048;
#pragma unroll
        for (int i = 0; i < 2; i++) {
            const int rl0 = wm * 32 + i * 16 + g;
            const float iv0 = inv_sm[rl0], iv1 = inv_sm[rl0 + 8];
            const int m_0 = m0 + rl0;
#pragma unroll
            for (int j = 0; j < 8; j++) {
                const int c0 = j * 8 + 2 * t;
                const float v0 = (ctxa[i][j][0] + ex_[(i * 16 + g) * 64 + c0])     * iv0;
                const float v1 = (ctxa[i][j][1] + ex_[(i * 16 + g) * 64 + c0 + 1]) * iv0;
                const float v2 = (ctxa[i][j][2] + ex_[(i * 16 + g + 8) * 64 + c0])     * iv1;
                const float v3 = (ctxa[i][j][3] + ex_[(i * 16 + g + 8) * 64 + c0 + 1]) * iv1;
                __half* d0 = ctx + ((long long)bb * S + m_0) * E + h * D + c0;
                __half* d1 = ctx + ((long long)bb * S + m_0 + 8) * E + h * D + c0;
                *(__half2*)d0 = __floats2half2_rn(v0, v1);
                *(__half2*)d1 = __floats2half2_rn(v2, v3);
            }
        }
    }
}

// ---------------- fp16 TN GEMM (256 thr / 8 warps, warp tile 32x64) ----------------
// MODE 0: fp32 out[m*N+n]+bias   MODE 5: fused QKV scatter (sector = n>>10; Q pre-scaled)
template <int BN, int MODE>
__global__ void __launch_bounds__(256, 2) gemm_h(
    const __half* __restrict__ A, const __half* __restrict__ Bm,
    void* __restrict__ Cv,
    const float* __restrict__ bias0, const float* __restrict__ bias1,
    const float* __restrict__ bias2,
    int N, int K)
{
    constexpr int ABUFB = 128 * 144;
    constexpr int BBUFB = BN * 144;
    constexpr int NTJ = BN / 16;

    extern __shared__ char smc[];
    const uint32_t sb = smem_u32(smc);
    const int tid = threadIdx.x, lane = tid & 31, wid = tid >> 5;
    const int wm = wid >> 1, wn = wid & 1;
    const int g = lane >> 2, t = lane & 3;
    const int m0 = blockIdx.y * 128, n0 = blockIdx.x * BN;

    float acc[2][NTJ][4];
#pragma unroll
    for (int i = 0; i < 2; i++)
#pragma unroll
        for (int j = 0; j < NTJ; j++)
#pragma unroll
            for (int r = 0; r < 4; r++) acc[i][j][r] = 0.f;

    auto load = [&](int chunk, int buf) {
        const int k0 = chunk * 64;
        const uint32_t ad = sb + (uint32_t)buf * ABUFB;
#pragma unroll
        for (int l = 0; l < 4; l++) {
            const int lin = tid + l * 256, row = lin >> 3, kq = lin & 7;
            const __half* src = A + (long long)(m0 + row) * K + k0 + kq * 8;
            asm volatile("cp.async.cg.shared.global [%0], [%1], 16;"
                         :: "r"(ad + row * 144 + kq * 16), "l"(src));
        }
        const uint32_t bd = sb + (uint32_t)(3 * ABUFB + buf * BBUFB);
#pragma unroll
        for (int l = 0; l < BN / 32; l++) {
            const int lin = tid + l * 256, row = lin >> 3, kq = lin & 7;
            const __half* src = Bm + (long long)(n0 + row) * K + k0 + kq * 8;
            asm volatile("cp.async.cg.shared.global [%0], [%1], 16;"
                         :: "r"(bd + row * 144 + kq * 16), "l"(src));
        }
        asm volatile("cp.async.commit_group;" ::: "memory");
    };

    const uint32_t a_lane = (uint32_t)((lane & 15) * 144 + ((lane >> 4) << 4));
    const uint32_t b_lane = (uint32_t)((((lane & 7) | ((lane >> 4) << 3)) * 144) + ((lane & 8) << 1));

    auto compute = [&](int buf) {
        const uint32_t abase = sb + (uint32_t)buf * ABUFB + (uint32_t)(wm * 32) * 144 + a_lane;
        const uint32_t bbase = sb + (uint32_t)(3 * ABUFB + buf * BBUFB)
                             + (uint32_t)(wn * (BN / 2)) * 144 + b_lane;
        uint32_t bf[2][NTJ][2];
#pragma unroll
        for (int jp = 0; jp < NTJ / 2; jp++)
            LDSM4(bf[0][2 * jp][0], bf[0][2 * jp][1], bf[0][2 * jp + 1][0], bf[0][2 * jp + 1][1],
                  bbase + jp * 16 * 144);
#pragma unroll
        for (int ks = 0; ks < 4; ks++) {
            const int cur = ks & 1;
            uint32_t af[2][4];
            LDSM4(af[0][0], af[0][1], af[0][2], af[0][3], abase + ks * 32);
            LDSM4(af[1][0], af[1][1], af[1][2], af[1][3], abase + 16 * 144 + ks * 32);
            if (ks < 3) {
#pragma unroll
                for (int jp = 0; jp < NTJ / 2; jp++)
                    LDSM4(bf[cur ^ 1][2 * jp][0], bf[cur ^ 1][2 * jp][1],
                          bf[cur ^ 1][2 * jp + 1][0], bf[cur ^ 1][2 * jp + 1][1],
                          bbase + jp * 16 * 144 + (ks + 1) * 32);
            }
#pragma unroll
            for (int i = 0; i < 2; i++)
#pragma unroll
                for (int j = 0; j < NTJ; j++)
                    mma16(acc[i][j], af[i], bf[cur][j]);
        }
    };

    const int NC = K / 64;
    load(0, 0);
    if (NC > 1) load(1, 1);
    for (int c = 0; c < NC; c++) {
        if (c + 1 < NC) asm volatile("cp.async.wait_group 1;" ::: "memory");
        else            asm volatile("cp.async.wait_group 0;" ::: "memory");
        __syncthreads();
        if (c + 2 < NC) load(c + 2, (c + 2) % 3);
        compute(c % 3);
    }

    float* Cf = (float*)Cv;
    const int sec = n0 >> 10;
    const float* bsel = (MODE == 5) ? (sec == 0 ? bias0 : sec == 1 ? bias1 : bias2) : bias0;
#pragma unroll
    for (int i = 0; i < 2; i++) {
        const int r0 = m0 + wm * 32 + i * 16 + g;
#pragma unroll
        for (int j = 0; j < NTJ; j++) {
            const int cn = n0 + wn * (BN / 2) + j * 8 + 2 * t;
            float c0 = acc[i][j][0], c1 = acc[i][j][1];
            float c2 = acc[i][j][2], c3 = acc[i][j][3];
            if constexpr (MODE == 0) {
                const float b0 = bias0[cn], b1 = bias0[cn + 1];
                *(float2*)&Cf[(long long)r0 * N + cn]       = make_float2(c0 + b0, c1 + b1);
                *(float2*)&Cf[(long long)(r0 + 8) * N + cn] = make_float2(c2 + b0, c3 + b1);
            } else {  // MODE 5
                const int nn = cn & 1023;
                const float b0 = bsel[nn], b1 = bsel[nn + 1];
                const int hh = nn >> 6, d = nn & (D - 1);
                if (sec < 2) {
                    const float sc = (sec == 0) ? QSCALE : 1.f;
                    __half* dst = sec == 0 ? g_Qh : g_Kh;
                    auto idx = [&](int m) {
                        return (((long long)(m >> 11) * H + hh) * S + (m & (S - 1))) * D + d;
                    };
                    *(__half2*)&dst[idx(r0)]     = __floats2half2_rn((c0 + b0) * sc, (c1 + b1) * sc);
                    *(__half2*)&dst[idx(r0 + 8)] = __floats2half2_rn((c2 + b0) * sc, (c3 + b1) * sc);
                } else {
                    auto idx = [&](int m, int dd) {
                        return (((long long)(m >> 11) * H + hh) * D + dd) * S + (m & (S - 1));
                    };
                    g_Vth[idx(r0, d)]         = __float2half_rn(c0 + b0);
                    g_Vth[idx(r0, d + 1)]     = __float2half_rn(c1 + b1);
                    g_Vth[idx(r0 + 8, d)]     = __float2half_rn(c2 + b0);
                    g_Vth[idx(r0 + 8, d + 1)] = __float2half_rn(c3 + b1);
                }
            }
        }
    }
}

// ---------------- head average ----------------
__global__ void __launch_bounds__(256) avg_heads(const __half* __restrict__ Ph,
                                                 const float* __restrict__ invs,
                                                 float* __restrict__ attn)
{
    const int sq = blockIdx.x, b = blockIdx.y;
    const int c = threadIdx.x * 8;
    const __half* p = Ph + (((long long)b * H) * S + sq) * S + c;
    const float* iv = invs + (long long)b * H * S + sq;

    float a[8] = {0.f, 0.f, 0.f, 0.f, 0.f, 0.f, 0.f, 0.f};
#pragma unroll
    for (int h = 0; h < H; h++) {
        const float inv = iv[(long long)h * S];
        uint2 u0 = *(const uint2*)(p);
        uint2 u1 = *(const uint2*)(p + 4);
        float2 f0 = __half22float2(*reinterpret_cast<__half2*>(&u0.x));
        float2 f1 = __half22float2(*reinterpret_cast<__half2*>(&u0.y));
        float2 f2 = __half22float2(*reinterpret_cast<__half2*>(&u1.x));
        float2 f3 = __half22float2(*reinterpret_cast<__half2*>(&u1.y));
        a[0] += f0.x * inv; a[1] += f0.y * inv;
        a[2] += f1.x * inv; a[3] += f1.y * inv;
        a[4] += f2.x * inv; a[5] += f2.y * inv;
        a[6] += f3.x * inv; a[7] += f3.y * inv;
        p += (long long)S * S;
    }
    const float s16 = 1.f / 16.f;
    float* o = attn + ((long long)b * S + sq) * S + c;
    *(float4*)(o)     = make_float4(a[0] * s16, a[1] * s16, a[2] * s16, a[3] * s16);
    *(float4*)(o + 4) = make_float4(a[4] * s16, a[5] * s16, a[6] * s16, a[7] * s16);
}

// ---------------- launch ----------------
extern "C" void kernel_launch(void* const* d_in, const int* in_sizes, int n_in,
                              void* d_out, int out_size)
{
    (void)in_sizes; (void)n_in; (void)out_size;
    const float* x  = (const float*)d_in[0];
    const float* Wq = (const float*)d_in[1];
    const float* bq = (const float*)d_in[2];
    const float* Wk = (const float*)d_in[3];
    const float* bk = (const float*)d_in[4];
    const float* Wv = (const float*)d_in[5];
    const float* bv = (const float*)d_in[6];
    const float* Wo = (const float*)d_in[7];
    const float* bo = (const float*)d_in[8];
    float* out  = (float*)d_out;
    float* attn = out + (long long)B * S * E;

    __half *pxh, *pWh, *pQ, *pK, *pVt, *pPh, *pCtx;
    float *pInv;
    cudaGetSymbolAddress((void**)&pxh, g_xh);
    cudaGetSymbolAddress((void**)&pWh, g_Wh);
    cudaGetSymbolAddress((void**)&pQ, g_Qh);
    cudaGetSymbolAddress((void**)&pK, g_Kh);
    cudaGetSymbolAddress((void**)&pVt, g_Vth);
    cudaGetSymbolAddress((void**)&pPh, g_Ph);
    cudaGetSymbolAddress((void**)&pInv, g_invs);
    cudaGetSymbolAddress((void**)&pCtx, g_ctxh);

    constexpr int SMEM_G    = 3 * 128 * 144 + 3 * 128 * 144;          // 110592
    constexpr int SMEM_QKPV = 18432 + 3 * 18432 + 3 * 17408 + 4608;   // 130560
    cudaFuncSetAttribute(gemm_h<128, 0>, cudaFuncAttributeMaxDynamicSharedMemorySize, SMEM_G);
    cudaFuncSetAttribute(gemm_h<128, 5>, cudaFuncAttributeMaxDynamicSharedMemorySize, SMEM_G);
    cudaFuncSetAttribute(qk_pv,          cudaFuncAttributeMaxDynamicSharedMemorySize, SMEM_QKPV);

    // merged fp32 -> fp16 conversions (x + 4 weights, one launch)
    f2h5<<<(unsigned)(NX / 1024 + 4 * (NW / 1024)), 256>>>(x, Wq, Wk, Wv, Wo, pxh, pWh);

    // Fused QKV projection (N = 3072); Q sector pre-scaled by QSCALE
    dim3 gqkv(3 * E / 128, MALL / 128, 1);
    gemm_h<128, 5><<<gqkv, 256, SMEM_G>>>(pxh, pWh, nullptr, bq, bk, bv, 3 * E, E);

    // Fused QK -> exp2(f16x2) -> Ph/invs + P@V -> ctx (single launch, full grid)
    qk_pv<<<dim3(S / 128, B * H), 256, SMEM_QKPV>>>(pQ, pK, pVt, pPh, pInv, pCtx);

    // Fork: head-average || out-projection
    const bool forked = g_async.ok;
    if (forked) {
        cudaEventRecord(g_async.e1, 0);
        cudaStreamWaitEvent(g_async.s2, g_async.e1, 0);
        avg_heads<<<dim3(S, B), 256, 0, g_async.s2>>>(pPh, pInv, attn);
        cudaEventRecord(g_async.e2, g_async.s2);
    } else {
        avg_heads<<<dim3(S, B), 256>>>(pPh, pInv, attn);
    }

    dim3 gproj(E / 128, MALL / 128, 1);
    gemm_h<128, 0><<<gproj, 256, SMEM_G>>>(pCtx, pWh + 3ll * E * E, out, bo,
                                           nullptr, nullptr, E, E);

    if (forked) cudaStreamWaitEvent(0, g_async.e2, 0);
}

// round 16
// speedup vs baseline: 1.1086x; 1.0224x over previous
#include <cuda_runtime.h>
#include <cuda_fp16.h>
#include <cstdint>
#include <cfloat>

namespace {
constexpr int S = 2048, E = 1024, H = 16, D = 64, B = 4;
constexpr int MALL = B * S;  // 8192
constexpr long long NX = (long long)MALL * E;   // x elems
constexpr long long NW = (long long)E * E;      // per-W elems
}

// Scratch (allocation-free: __device__ globals)
__device__ __half g_xh [(size_t)MALL * E];        // x in fp16
__device__ __half g_Wh [(size_t)4 * E * E];       // Wq|Wk|Wv|Wo fp16 (QKV contiguous)
__device__ __half g_Qh [(size_t)B * H * S * D];   // [B,H,S,D], pre-scaled by 0.125*log2(e)
__device__ __half g_Kh [(size_t)B * H * S * D];   // [B,H,S,D]
__device__ __half g_Vth[(size_t)B * H * D * S];   // [B,H,D,S]
__device__ __half g_Ph [(size_t)B * H * S * S];   // UNNORMALIZED exp(scores), fp16
__device__ float  g_invs[(size_t)B * H * S];      // 1/rowsum per (b,h,s)
__device__ __half g_ctxh[(size_t)B * S * E];      // [B,S,E]

namespace {
struct AsyncCtx {
    cudaStream_t s2 = nullptr;
    cudaEvent_t e1 = nullptr, e2 = nullptr;
    bool ok = false;
    AsyncCtx() {
        ok = cudaStreamCreateWithFlags(&s2, cudaStreamNonBlocking) == cudaSuccess
          && cudaEventCreateWithFlags(&e1, cudaEventDisableTiming) == cudaSuccess
          && cudaEventCreateWithFlags(&e2, cudaEventDisableTiming) == cudaSuccess;
    }
};
AsyncCtx g_async;
}

__device__ __forceinline__ uint32_t smem_u32(const void* p) {
    uint32_t a;
    asm("{ .reg .u64 t; cvta.to.shared.u64 t, %1; cvt.u32.u64 %0, t; }" : "=r"(a) : "l"(p));
    return a;
}
__device__ __forceinline__ void mma16(float* c, const uint32_t* a, const uint32_t* b) {
    asm volatile(
        "mma.sync.aligned.m16n8k16.row.col.f32.f16.f16.f32 "
        "{%0,%1,%2,%3}, {%4,%5,%6,%7}, {%8,%9}, {%0,%1,%2,%3};"
        : "+f"(c[0]), "+f"(c[1]), "+f"(c[2]), "+f"(c[3])
        : "r"(a[0]), "r"(a[1]), "r"(a[2]), "r"(a[3]), "r"(b[0]), "r"(b[1]));
}
__device__ __forceinline__ uint32_t packh2(float a, float b) {
    __half2 h = __floats2half2_rn(a, b);
    return *reinterpret_cast<uint32_t*>(&h);
}
// fp16x2 exp2: one MUFU per pair
__device__ __forceinline__ uint32_t h2ex2(uint32_t x) {
    uint32_t r;
    asm("ex2.approx.f16x2 %0, %1;" : "=r"(r) : "r"(x));
    return r;
}
#define LDSM4(r0, r1, r2, r3, addr) \
    asm volatile("ldmatrix.sync.aligned.m8n8.x4.shared.b16 {%0,%1,%2,%3}, [%4];" \
        : "=r"(r0), "=r"(r1), "=r"(r2), "=r"(r3) : "r"(addr))

// exp2 pre-scale folded into Q: exp(s*0.125) == exp2(s*QSCALE)
#define QSCALE 0.1803368801111204f   // 0.125 * log2(e)

// ---------------- merged fp32 -> fp16 convert (x + 4 weights, one launch) ----------------
__global__ void __launch_bounds__(256) f2h5(
    const float* __restrict__ x,
    const float* __restrict__ Wq, const float* __restrict__ Wk,
    const float* __restrict__ Wv, const float* __restrict__ Wo,
    __half* __restrict__ xh, __half* __restrict__ Wh)
{
    constexpr int XCTAS = (int)(NX / 1024);   // 8192
    constexpr int WCTAS = (int)(NW / 1024);   // 1024
    const int bid = blockIdx.x;
    const float* src;
    __half* dst;
    long long off;
    if (bid < XCTAS) {
        src = x; dst = xh;
        off = (long long)bid * 1024 + threadIdx.x * 4;
    } else {
        const int w = (bid - XCTAS) / WCTAS;       // 0..3
        const int wo = (bid - XCTAS) % WCTAS;
        src = (w == 0) ? Wq : (w == 1) ? Wk : (w == 2) ? Wv : Wo;
        dst = Wh + (long long)w * NW;
        off = (long long)wo * 1024 + threadIdx.x * 4;
    }
    float4 v = *(const float4*)(src + off);
    *(__half2*)(dst + off)     = __floats2half2_rn(v.x, v.y);
    *(__half2*)(dst + off + 2) = __floats2half2_rn(v.z, v.w);
}

// ---------------- fused QK^T -> exp2(f16x2) -> {Ph, rowsums} + P@V -> ctx ----------------
// grid (S/128, B*H), 256 threads. Q pre-scaled; probs = ex2.f16x2(pack(scores)).
// exp interleaved with PV at k-chunk granularity (MUFU hides under tensor issue).
__global__ void __launch_bounds__(256) qk_pv(
    const __half* __restrict__ Qg, const __half* __restrict__ Kg,
    const __half* __restrict__ Vtg,
    __half* __restrict__ Ph, float* __restrict__ invs, __half* __restrict__ ctx)
{
    constexpr int KB_ = 128 * 144;
    constexpr int VB_ = 64 * 272;
    constexpr int QOFF = 0;
    constexpr int KOFF = KB_;
    constexpr int VOFF = KOFF + 3 * KB_;
    constexpr int REDOFF = VOFF + 3 * VB_;
    constexpr int INVOFF = REDOFF + 4096;
    constexpr int EXOFF = KOFF;

    extern __shared__ char smc[];
    const uint32_t sb = smem_u32(smc);
    const int tid = threadIdx.x, lane = tid & 31, wid = tid >> 5;
    const int wm = wid >> 1, wn = wid & 1;
    const int g = lane >> 2, t = lane & 3;
    const int m0 = blockIdx.x * 128;
    const int bh = blockIdx.y;
    const int bb = bh >> 4, h = bh & (H - 1);
    const __half* __restrict__ Qb = Qg + ((long long)bh * S + m0) * D;
    const __half* __restrict__ Kb = Kg + (long long)bh * S * D;
    const __half* __restrict__ Vb = Vtg + (long long)bh * D * S;
    __half* __restrict__ Pb = Ph + ((long long)bh * S + m0) * S;

#pragma unroll
    for (int l = 0; l < 4; l++) {
        const int lin = tid + l * 256, row = lin >> 3, kq = lin & 7;
        asm volatile("cp.async.cg.shared.global [%0], [%1], 16;"
                     :: "r"(sb + QOFF + row * 144 + kq * 16), "l"(Qb + row * D + kq * 8));
    }
    auto loadKV = [&](int nt, int buf) {
        const __half* ks = Kb + (long long)nt * 128 * D;
        const uint32_t kd = sb + KOFF + (uint32_t)buf * KB_;
#pragma unroll
        for (int l = 0; l < 4; l++) {
            const int lin = tid + l * 256, row = lin >> 3, kq = lin & 7;
            asm volatile("cp.async.cg.shared.global [%0], [%1], 16;"
                         :: "r"(kd + row * 144 + kq * 16), "l"(ks + row * D + kq * 8));
        }
        const __half* vs = Vb + nt * 128;
        const uint32_t vd = sb + VOFF + (uint32_t)buf * VB_;
#pragma unroll
        for (int l = 0; l < 4; l++) {
            const int lin = tid + l * 256, row = lin >> 4, sg = lin & 15;
            asm volatile("cp.async.cg.shared.global [%0], [%1], 16;"
                         :: "r"(vd + row * 272 + sg * 16), "l"(vs + (long long)row * S + sg * 8));
        }
        asm volatile("cp.async.commit_group;" ::: "memory");
    };

    const uint32_t a_lane = (uint32_t)((lane & 15) * 144 + ((lane >> 4) << 4));
    const uint32_t b_lane = (uint32_t)((((lane & 7) | ((lane >> 4) << 3)) * 144) + ((lane & 8) << 1));
    const uint32_t bv_lane = (uint32_t)((((lane & 7) | ((lane >> 4) << 3)) * 272) + ((lane & 8) << 1));
    const uint32_t abase = sb + QOFF + (uint32_t)(wm * 32) * 144 + a_lane;

    loadKV(0, 0);
    loadKV(1, 1);

    float rs[4] = {0.f, 0.f, 0.f, 0.f};
    float ctxa[2][8][4];
#pragma unroll
    for (int i = 0; i < 2; i++)
#pragma unroll
        for (int j = 0; j < 8; j++)
#pragma unroll
            for (int r = 0; r < 4; r++) ctxa[i][j][r] = 0.f;

    for (int nt = 0; nt < 16; nt++) {
        if (nt + 1 < 16) asm volatile("cp.async.wait_group 1;" ::: "memory");
        else             asm volatile("cp.async.wait_group 0;" ::: "memory");
        __syncthreads();
        if (nt + 2 < 16) loadKV(nt + 2, (nt + 2) % 3);

        float acc[2][8][4];
#pragma unroll
        for (int i = 0; i < 2; i++)
#pragma unroll
            for (int j = 0; j < 8; j++)
#pragma unroll
                for (int r = 0; r < 4; r++) acc[i][j][r] = 0.f;

        const uint32_t bbase = sb + KOFF + (uint32_t)(nt % 3) * KB_
                             + (uint32_t)(wn * 64) * 144 + b_lane;
        uint32_t bf[2][8][2];
#pragma unroll
        for (int jp = 0; jp < 4; jp++)
            LDSM4(bf[0][2 * jp][0], bf[0][2 * jp][1], bf[0][2 * jp + 1][0], bf[0][2 * jp + 1][1],
                  bbase + jp * 16 * 144);
#pragma unroll
        for (int ks = 0; ks < 4; ks++) {
            const int cur = ks & 1;
            uint32_t af[2][4];
            LDSM4(af[0][0], af[0][1], af[0][2], af[0][3], abase + ks * 32);
            LDSM4(af[1][0], af[1][1], af[1][2], af[1][3], abase + 16 * 144 + ks * 32);
            if (ks < 3) {
#pragma unroll
                for (int jp = 0; jp < 4; jp++)
                    LDSM4(bf[cur ^ 1][2 * jp][0], bf[cur ^ 1][2 * jp][1],
                          bf[cur ^ 1][2 * jp + 1][0], bf[cur ^ 1][2 * jp + 1][1],
                          bbase + jp * 16 * 144 + (ks + 1) * 32);
            }
#pragma unroll
            for (int i = 0; i < 2; i++)
#pragma unroll
                for (int j = 0; j < 8; j++)
                    mma16(acc[i][j], af[i], bf[cur][j]);
        }

        // Interleaved exp + PV: per k-chunk kb, LDSM V frags, exp 4 score pairs
        // (-> Ph store + rowsums + PV A-frags), then 16 PV MMAs.
        const int n0 = nt * 128;
        const uint32_t vbase = sb + VOFF + (uint32_t)(nt % 3) * VB_ + bv_lane
                             + (uint32_t)(wn * 64) * 2;
#pragma unroll
        for (int kb = 0; kb < 4; kb++) {
            uint32_t bv[8][2];
#pragma unroll
            for (int jp = 0; jp < 4; jp++)
                LDSM4(bv[2 * jp][0], bv[2 * jp][1], bv[2 * jp + 1][0], bv[2 * jp + 1][1],
                      vbase + jp * 16 * 272 + kb * 32);
            uint32_t pa[2][4];
#pragma unroll
            for (int i = 0; i < 2; i++) {
                const int r0 = wm * 32 + i * 16 + g;
#pragma unroll
                for (int jj = 0; jj < 2; jj++) {
                    const int j = 2 * kb + jj;
                    const int cn = n0 + wn * 64 + j * 8 + 2 * t;
                    const uint32_t e01 = h2ex2(packh2(acc[i][j][0], acc[i][j][1]));
                    const uint32_t e23 = h2ex2(packh2(acc[i][j][2], acc[i][j][3]));
                    pa[i][2 * jj]     = e01;
                    pa[i][2 * jj + 1] = e23;
                    *(uint32_t*)&Pb[(long long)r0 * S + cn]       = e01;
                    *(uint32_t*)&Pb[(long long)(r0 + 8) * S + cn] = e23;
                    const float2 f01 = __half22float2(*reinterpret_cast<const __half2*>(&e01));
                    const float2 f23 = __half22float2(*reinterpret_cast<const __half2*>(&e23));
                    rs[2 * i]     += f01.x + f01.y;
                    rs[2 * i + 1] += f23.x + f23.y;
                }
            }
#pragma unroll
            for (int i = 0; i < 2; i++)
#pragma unroll
                for (int j = 0; j < 8; j++)
                    mma16(ctxa[i][j], pa[i], bv[j]);
        }
    }

    __syncthreads();
    float* red = (float*)(smc + REDOFF);
    float* inv_sm = (float*)(smc + INVOFF);
    const int slot = wn * 4 + t;
#pragma unroll
    for (int i = 0; i < 2; i++) {
        red[(wm * 32 + i * 16 + g) * 8 + slot]     = rs[2 * i];
        red[(wm * 32 + i * 16 + g + 8) * 8 + slot] = rs[2 * i + 1];
    }
    __syncthreads();
    if (tid < 128) {
        float s = 0.f;
#pragma unroll
        for (int q = 0; q < 8; q++) s += red[tid * 8 + q];
        const float iv = 1.f / s;
        inv_sm[tid] = iv;
        invs[(long long)bh * S + m0 + tid] = iv;
    }
    if (wn == 1) {
        float* ex_ = (float*)(smc + EXOFF) + wm * 2048;
#pragma unroll
        for (int i = 0; i < 2; i++)
#pragma unroll
            for (int j = 0; j < 8; j++) {
                const int c0 = j * 8 + 2 * t;
                ex_[(i * 16 + g) * 64 + c0]           = ctxa[i][j][0];
                ex_[(i * 16 + g) * 64 + c0 + 1]       = ctxa[i][j][1];
                ex_[(i * 16 + g + 8) * 64 + c0]       = ctxa[i][j][2];
                ex_[(i * 16 + g + 8) * 64 + c0 + 1]   = ctxa[i][j][3];
            }
    }
    __syncthreads();
    if (wn == 0) {
        const float* ex_ = (const float*)(smc + EXOFF) + wm * 2048;
#pragma unroll
        for (int i = 0; i < 2; i++) {
            const int rl0 = wm * 32 + i * 16 + g;
            const float iv0 = inv_sm[rl0], iv1 = inv_sm[rl0 + 8];
            const int m_0 = m0 + rl0;
#pragma unroll
            for (int j = 0; j < 8; j++) {
                const int c0 = j * 8 + 2 * t;
                const float v0 = (ctxa[i][j][0] + ex_[(i * 16 + g) * 64 + c0])     * iv0;
                const float v1 = (ctxa[i][j][1] + ex_[(i * 16 + g) * 64 + c0 + 1]) * iv0;
                const float v2 = (ctxa[i][j][2] + ex_[(i * 16 + g + 8) * 64 + c0])     * iv1;
                const float v3 = (ctxa[i][j][3] + ex_[(i * 16 + g + 8) * 64 + c0 + 1]) * iv1;
                __half* d0 = ctx + ((long long)bb * S + m_0) * E + h * D + c0;
                __half* d1 = ctx + ((long long)bb * S + m_0 + 8) * E + h * D + c0;
                *(__half2*)d0 = __floats2half2_rn(v0, v1);
                *(__half2*)d1 = __floats2half2_rn(v2, v3);
            }
        }
    }
}

// ---------------- fp16 TN GEMM (256 thr / 8 warps, warp tile 32x64) ----------------
// MODE 0: fp32 out[m*N+n]+bias   MODE 5: fused QKV scatter (sector = n>>10; Q pre-scaled)
template <int BN, int MODE>
__global__ void __launch_bounds__(256, 2) gemm_h(
    const __half* __restrict__ A, const __half* __restrict__ Bm,
    void* __restrict__ Cv,
    const float* __restrict__ bias0, const float* __restrict__ bias1,
    const float* __restrict__ bias2,
    int N, int K)
{
    constexpr int ABUFB = 128 * 144;
    constexpr int BBUFB = BN * 144;
    constexpr int NTJ = BN / 16;

    extern __shared__ char smc[];
    const uint32_t sb = smem_u32(smc);
    const int tid = threadIdx.x, lane = tid & 31, wid = tid >> 5;
    const int wm = wid >> 1, wn = wid & 1;
    const int g = lane >> 2, t = lane & 3;
    const int m0 = blockIdx.y * 128, n0 = blockIdx.x * BN;

    float acc[2][NTJ][4];
#pragma unroll
    for (int i = 0; i < 2; i++)
#pragma unroll
        for (int j = 0; j < NTJ; j++)
#pragma unroll
            for (int r = 0; r < 4; r++) acc[i][j][r] = 0.f;

    auto load = [&](int chunk, int buf) {
        const int k0 = chunk * 64;
        const uint32_t ad = sb + (uint32_t)buf * ABUFB;
#pragma unroll
        for (int l = 0; l < 4; l++) {
            const int lin = tid + l * 256, row = lin >> 3, kq = lin & 7;
            const __half* src = A + (long long)(m0 + row) * K + k0 + kq * 8;
            asm volatile("cp.async.cg.shared.global [%0], [%1], 16;"
                         :: "r"(ad + row * 144 + kq * 16), "l"(src));
        }
        const uint32_t bd = sb + (uint32_t)(3 * ABUFB + buf * BBUFB);
#pragma unroll
        for (int l = 0; l < BN / 32; l++) {
            const int lin = tid + l * 256, row = lin >> 3, kq = lin & 7;
            const __half* src = Bm + (long long)(n0 + row) * K + k0 + kq * 8;
            asm volatile("cp.async.cg.shared.global [%0], [%1], 16;"
                         :: "r"(bd + row * 144 + kq * 16), "l"(src));
        }
        asm volatile("cp.async.commit_group;" ::: "memory");
    };

    const uint32_t a_lane = (uint32_t)((lane & 15) * 144 + ((lane >> 4) << 4));
    const uint32_t b_lane = (uint32_t)((((lane & 7) | ((lane >> 4) << 3)) * 144) + ((lane & 8) << 1));

    auto compute = [&](int buf) {
        const uint32_t abase = sb + (uint32_t)buf * ABUFB + (uint32_t)(wm * 32) * 144 + a_lane;
        const uint32_t bbase = sb + (uint32_t)(3 * ABUFB + buf * BBUFB)
                             + (uint32_t)(wn * (BN / 2)) * 144 + b_lane;
        uint32_t bf[2][NTJ][2];
#pragma unroll
        for (int jp = 0; jp < NTJ / 2; jp++)
            LDSM4(bf[0][2 * jp][0], bf[0][2 * jp][1], bf[0][2 * jp + 1][0], bf[0][2 * jp + 1][1],
                  bbase + jp * 16 * 144);
#pragma unroll
        for (int ks = 0; ks < 4; ks++) {
            const int cur = ks & 1;
            uint32_t af[2][4];
            LDSM4(af[0][0], af[0][1], af[0][2], af[0][3], abase + ks * 32);
            LDSM4(af[1][0], af[1][1], af[1][2], af[1][3], abase + 16 * 144 + ks * 32);
            if (ks < 3) {
#pragma unroll
                for (int jp = 0; jp < NTJ / 2; jp++)
                    LDSM4(bf[cur ^ 1][2 * jp][0], bf[cur ^ 1][2 * jp][1],
                          bf[cur ^ 1][2 * jp + 1][0], bf[cur ^ 1][2 * jp + 1][1],
                          bbase + jp * 16 * 144 + (ks + 1) * 32);
            }
#pragma unroll
            for (int i = 0; i < 2; i++)
#pragma unroll
                for (int j = 0; j < NTJ; j++)
                    mma16(acc[i][j], af[i], bf[cur][j]);
        }
    };

    const int NC = K / 64;
    load(0, 0);
    if (NC > 1) load(1, 1);
    for (int c = 0; c < NC; c++) {
        if (c + 1 < NC) asm volatile("cp.async.wait_group 1;" ::: "memory");
        else            asm volatile("cp.async.wait_group 0;" ::: "memory");
        __syncthreads();
        if (c + 2 < NC) load(c + 2, (c + 2) % 3);
        compute(c % 3);
    }

    float* Cf = (float*)Cv;
    const int sec = n0 >> 10;
    const float* bsel = (MODE == 5) ? (sec == 0 ? bias0 : sec == 1 ? bias1 : bias2) : bias0;
#pragma unroll
    for (int i = 0; i < 2; i++) {
        const int r0 = m0 + wm * 32 + i * 16 + g;
#pragma unroll
        for (int j = 0; j < NTJ; j++) {
            const int cn = n0 + wn * (BN / 2) + j * 8 + 2 * t;
            float c0 = acc[i][j][0], c1 = acc[i][j][1];
            float c2 = acc[i][j][2], c3 = acc[i][j][3];
            if constexpr (MODE == 0) {
                const float b0 = bias0[cn], b1 = bias0[cn + 1];
                *(float2*)&Cf[(long long)r0 * N + cn]       = make_float2(c0 + b0, c1 + b1);
                *(float2*)&Cf[(long long)(r0 + 8) * N + cn] = make_float2(c2 + b0, c3 + b1);
            } else {  // MODE 5
                const int nn = cn & 1023;
                const float b0 = bsel[nn], b1 = bsel[nn + 1];
                const int hh = nn >> 6, d = nn & (D - 1);
                if (sec < 2) {
                    const float sc = (sec == 0) ? QSCALE : 1.f;
                    __half* dst = sec == 0 ? g_Qh : g_Kh;
                    auto idx = [&](int m) {
                        return (((long long)(m >> 11) * H + hh) * S + (m & (S - 1))) * D + d;
                    };
                    *(__half2*)&dst[idx(r0)]     = __floats2half2_rn((c0 + b0) * sc, (c1 + b1) * sc);
                    *(__half2*)&dst[idx(r0 + 8)] = __floats2half2_rn((c2 + b0) * sc, (c3 + b1) * sc);
                } else {
                    auto idx = [&](int m, int dd) {
                        return (((long long)(m >> 11) * H + hh) * D + dd) * S + (m & (S - 1));
                    };
                    g_Vth[idx(r0, d)]         = __float2half_rn(c0 + b0);
                    g_Vth[idx(r0, d + 1)]     = __float2half_rn(c1 + b1);
                    g_Vth[idx(r0 + 8, d)]     = __float2half_rn(c2 + b0);
                    g_Vth[idx(r0 + 8, d + 1)] = __float2half_rn(c3 + b1);
                }
            }
        }
    }
}

// ---------------- head average ----------------
__global__ void __launch_bounds__(256) avg_heads(const __half* __restrict__ Ph,
                                                 const float* __restrict__ invs,
                                                 float* __restrict__ attn)
{
    const int sq = blockIdx.x, b = blockIdx.y;
    const int c = threadIdx.x * 8;
    const __half* p = Ph + (((long long)b * H) * S + sq) * S + c;
    const float* iv = invs + (long long)b * H * S + sq;

    float a[8] = {0.f, 0.f, 0.f, 0.f, 0.f, 0.f, 0.f, 0.f};
#pragma unroll
    for (int h = 0; h < H; h++) {
        const float inv = iv[(long long)h * S];
        uint2 u0 = *(const uint2*)(p);
        uint2 u1 = *(const uint2*)(p + 4);
        float2 f0 = __half22float2(*reinterpret_cast<__half2*>(&u0.x));
        float2 f1 = __half22float2(*reinterpret_cast<__half2*>(&u0.y));
        float2 f2 = __half22float2(*reinterpret_cast<__half2*>(&u1.x));
        float2 f3 = __half22float2(*reinterpret_cast<__half2*>(&u1.y));
        a[0] += f0.x * inv; a[1] += f0.y * inv;
        a[2] += f1.x * inv; a[3] += f1.y * inv;
        a[4] += f2.x * inv; a[5] += f2.y * inv;
        a[6] += f3.x * inv; a[7] += f3.y * inv;
        p += (long long)S * S;
    }
    const float s16 = 1.f / 16.f;
    float* o = attn + ((long long)b * S + sq) * S + c;
    *(float4*)(o)     = make_float4(a[0] * s16, a[1] * s16, a[2] * s16, a[3] * s16);
    *(float4*)(o + 4) = make_float4(a[4] * s16, a[5] * s16, a[6] * s16, a[7] * s16);
}

// ---------------- launch ----------------
extern "C" void kernel_launch(void* const* d_in, const int* in_sizes, int n_in,
                              void* d_out, int out_size)
{
    (void)in_sizes; (void)n_in; (void)out_size;
    const float* x  = (const float*)d_in[0];
    const float* Wq = (const float*)d_in[1];
    const float* bq = (const float*)d_in[2];
    const float* Wk = (const float*)d_in[3];
    const float* bk = (const float*)d_in[4];
    const float* Wv = (const float*)d_in[5];
    const float* bv = (const float*)d_in[6];
    const float* Wo = (const float*)d_in[7];
    const float* bo = (const float*)d_in[8];
    float* out  = (float*)d_out;
    float* attn = out + (long long)B * S * E;

    __half *pxh, *pWh, *pQ, *pK, *pVt, *pPh, *pCtx;
    float *pInv;
    cudaGetSymbolAddress((void**)&pxh, g_xh);
    cudaGetSymbolAddress((void**)&pWh, g_Wh);
    cudaGetSymbolAddress((void**)&pQ, g_Qh);
    cudaGetSymbolAddress((void**)&pK, g_Kh);
    cudaGetSymbolAddress((void**)&pVt, g_Vth);
    cudaGetSymbolAddress((void**)&pPh, g_Ph);
    cudaGetSymbolAddress((void**)&pInv, g_invs);
    cudaGetSymbolAddress((void**)&pCtx, g_ctxh);

    constexpr int SMEM_G    = 3 * 128 * 144 + 3 * 128 * 144;          // 110592
    constexpr int SMEM_QKPV = 18432 + 3 * 18432 + 3 * 17408 + 4608;   // 130560
    cudaFuncSetAttribute(gemm_h<128, 0>, cudaFuncAttributeMaxDynamicSharedMemorySize, SMEM_G);
    cudaFuncSetAttribute(gemm_h<128, 5>, cudaFuncAttributeMaxDynamicSharedMemorySize, SMEM_G);
    cudaFuncSetAttribute(qk_pv,          cudaFuncAttributeMaxDynamicSharedMemorySize, SMEM_QKPV);

    // merged fp32 -> fp16 conversions (x + 4 weights, one launch)
    f2h5<<<(unsigned)(NX / 1024 + 4 * (NW / 1024)), 256>>>(x, Wq, Wk, Wv, Wo, pxh, pWh);

    // Fused QKV projection (N = 3072); Q sector pre-scaled by QSCALE
    dim3 gqkv(3 * E / 128, MALL / 128, 1);
    gemm_h<128, 5><<<gqkv, 256, SMEM_G>>>(pxh, pWh, nullptr, bq, bk, bv, 3 * E, E);

    // Fused QK -> exp2(f16x2) -> Ph/invs + P@V -> ctx (single launch, full grid)
    qk_pv<<<dim3(S / 128, B * H), 256, SMEM_QKPV>>>(pQ, pK, pVt, pPh, pInv, pCtx);

    // Fork: head-average || out-projection
    const bool forked = g_async.ok;
    if (forked) {
        cudaEventRecord(g_async.e1, 0);
        cudaStreamWaitEvent(g_async.s2, g_async.e1, 0);
        avg_heads<<<dim3(S, B), 256, 0, g_async.s2>>>(pPh, pInv, attn);
        cudaEventRecord(g_async.e2, g_async.s2);
    } else {
        avg_heads<<<dim3(S, B), 256>>>(pPh, pInv, attn);
    }

    dim3 gproj(E / 128, MALL / 128, 1);
    gemm_h<128, 0><<<gproj, 256, SMEM_G>>>(pCtx, pWh + 3ll * E * E, out, bo,
                                           nullptr, nullptr, E, E);

    if (forked) cudaStreamWaitEvent(0, g_async.e2, 0);
}